// round 1
// baseline (speedup 1.0000x reference)
#include <cuda_runtime.h>
#include <math.h>

// ---------------------------------------------------------------------------
// Problem constants
// ---------------------------------------------------------------------------
static constexpr int Bn = 32;
static constexpr int Sn = 1024;
static constexpr int En = 512;
static constexpr int Hn = 8;
static constexpr int Dn = 64;       // E / H
static constexpr int Ln = 2;
static constexpr int Mn = Bn * Sn;  // 32768 rows
static constexpr size_t ME = (size_t)Mn * En;  // 16,777,216 elements

// Scratch arena: X, Q, K, V, Attn  (5 * 64MB) + PE table (2MB)
__device__ float g_buf[5 * ME + (size_t)Sn * En];

// ---------------------------------------------------------------------------
// Positional encoding table: pe[s][e]
// ---------------------------------------------------------------------------
__global__ void pe_kernel(float* __restrict__ pe) {
    int idx = blockIdx.x * blockDim.x + threadIdx.x;
    if (idx >= Sn * En) return;
    int s = idx >> 9;          // / 512
    int e = idx & 511;
    float i2 = (float)(e & ~1);
    float div = __expf(i2 * (-9.210340371976184f / (float)En));  // -ln(10000)/E
    float a = (float)s * div;
    pe[idx] = (e & 1) ? cosf(a) : sinf(a);
}

// ---------------------------------------------------------------------------
// Embedding gather + PE add (float4 vectorized)
// ---------------------------------------------------------------------------
__global__ void embed_kernel(const int* __restrict__ tok,
                             const float* __restrict__ table,
                             const float* __restrict__ pe,
                             float* __restrict__ x) {
    int idx4 = blockIdx.x * blockDim.x + threadIdx.x;  // over M * E/4
    if (idx4 >= Mn * (En / 4)) return;
    int row = idx4 >> 7;       // / 128
    int d4  = idx4 & 127;
    int s   = row & (Sn - 1);
    int t   = tok[row];
    float4 tv = ((const float4*)table)[(size_t)t * 128 + d4];
    float4 pv = ((const float4*)pe)[(size_t)s * 128 + d4];
    float4 o;
    o.x = tv.x + pv.x; o.y = tv.y + pv.y; o.z = tv.z + pv.z; o.w = tv.w + pv.w;
    ((float4*)x)[idx4] = o;
}

// ---------------------------------------------------------------------------
// SGEMM: C[M,512] = A[M,512] @ W[512,512] (+ bias)    row-major everywhere
// RELU_RES: C = res + relu(acc + bias)   (used for O-projection, in-place X)
// 128x128x16 tile, 256 threads, 8x8 microtile.
// Thread column mapping: cols {tx*4..tx*4+3} and {64+tx*4 .. +3} for
// conflict-minimal float4 smem reads.
// ---------------------------------------------------------------------------
template <bool RELU_RES>
__global__ __launch_bounds__(256, 2)
void gemm512(const float* __restrict__ A, const float* __restrict__ W,
             const float* __restrict__ bias, const float* __restrict__ res,
             float* __restrict__ C) {
    __shared__ float As[16][128];
    __shared__ float Bs[16][128];
    const int tid = threadIdx.x;
    const int tx = tid & 15;
    const int ty = tid >> 4;
    const int row0 = blockIdx.y * 128;
    const int col0 = blockIdx.x * 128;

    float acc[8][8];
#pragma unroll
    for (int i = 0; i < 8; ++i)
#pragma unroll
        for (int j = 0; j < 8; ++j) acc[i][j] = 0.f;

    for (int k0 = 0; k0 < En; k0 += 16) {
        // load A tile 128x16 (transposed into As[k][m])
#pragma unroll
        for (int i = 0; i < 2; ++i) {
            int idx = tid + i * 256;          // over 512 float4
            int m  = idx >> 2;
            int kk = (idx & 3) << 2;
            float4 a = *(const float4*)&A[(size_t)(row0 + m) * En + k0 + kk];
            As[kk + 0][m] = a.x; As[kk + 1][m] = a.y;
            As[kk + 2][m] = a.z; As[kk + 3][m] = a.w;
        }
        // load B tile 16x128
#pragma unroll
        for (int i = 0; i < 2; ++i) {
            int idx = tid + i * 256;
            int kk = idx >> 5;
            int n4 = idx & 31;
            *(float4*)&Bs[kk][n4 << 2] =
                *(const float4*)&W[(size_t)(k0 + kk) * En + col0 + (n4 << 2)];
        }
        __syncthreads();
#pragma unroll
        for (int kk = 0; kk < 16; ++kk) {
            float a[8], b[8];
            *(float4*)&a[0] = *(const float4*)&As[kk][ty * 8];
            *(float4*)&a[4] = *(const float4*)&As[kk][ty * 8 + 4];
            *(float4*)&b[0] = *(const float4*)&Bs[kk][tx * 4];
            *(float4*)&b[4] = *(const float4*)&Bs[kk][64 + tx * 4];
#pragma unroll
            for (int i = 0; i < 8; ++i)
#pragma unroll
                for (int j = 0; j < 8; ++j)
                    acc[i][j] = fmaf(a[i], b[j], acc[i][j]);
        }
        __syncthreads();
    }

    // epilogue
    float4 bi0 = *(const float4*)&bias[col0 + tx * 4];
    float4 bi1 = *(const float4*)&bias[col0 + 64 + tx * 4];
#pragma unroll
    for (int i = 0; i < 8; ++i) {
        int m = row0 + ty * 8 + i;
        size_t off0 = (size_t)m * En + col0 + tx * 4;
        size_t off1 = off0 + 64;
        float4 v0, v1;
        v0.x = acc[i][0] + bi0.x; v0.y = acc[i][1] + bi0.y;
        v0.z = acc[i][2] + bi0.z; v0.w = acc[i][3] + bi0.w;
        v1.x = acc[i][4] + bi1.x; v1.y = acc[i][5] + bi1.y;
        v1.z = acc[i][6] + bi1.z; v1.w = acc[i][7] + bi1.w;
        if (RELU_RES) {
            float4 r0 = *(const float4*)&res[off0];
            float4 r1 = *(const float4*)&res[off1];
            v0.x = r0.x + fmaxf(v0.x, 0.f); v0.y = r0.y + fmaxf(v0.y, 0.f);
            v0.z = r0.z + fmaxf(v0.z, 0.f); v0.w = r0.w + fmaxf(v0.w, 0.f);
            v1.x = r1.x + fmaxf(v1.x, 0.f); v1.y = r1.y + fmaxf(v1.y, 0.f);
            v1.z = r1.z + fmaxf(v1.z, 0.f); v1.w = r1.w + fmaxf(v1.w, 0.f);
        }
        *(float4*)&C[off0] = v0;
        *(float4*)&C[off1] = v1;
    }
}

// ---------------------------------------------------------------------------
// Causal flash attention, fp32. One thread = one query row (q, o in regs).
// Block = 128 query rows of one (b,h). K/V staged in 32-row smem tiles.
// Layout [B,S,E] with head h at columns h*64..h*64+63.
// ---------------------------------------------------------------------------
static constexpr int KT = 32;

__global__ __launch_bounds__(128)
void attn_kernel(const float* __restrict__ Q, const float* __restrict__ Kg,
                 const float* __restrict__ Vg, float* __restrict__ Og) {
    __shared__ float Ks[KT][64];
    __shared__ float Vs[KT][64];
    const int b = blockIdx.z, h = blockIdx.y, qt = blockIdx.x;
    const int r = threadIdx.x;
    const int qg = qt * 128 + r;

    const float4* qp = (const float4*)(Q + ((size_t)(b * Sn + qg)) * En + h * Dn);
    float4 q4[16];
#pragma unroll
    for (int i = 0; i < 16; ++i) q4[i] = qp[i];
    float4 o4[16];
#pragma unroll
    for (int i = 0; i < 16; ++i) o4[i] = make_float4(0.f, 0.f, 0.f, 0.f);

    float mi = -1e30f, l = 0.f;
    const int nkt = qt * 4 + 4;  // key tiles up to & including the diagonal

    for (int kt = 0; kt < nkt; ++kt) {
        size_t base = ((size_t)(b * Sn + kt * KT)) * En + h * Dn;
#pragma unroll
        for (int i = 0; i < 4; ++i) {
            int idx = r + i * 128;           // 512 float4 per array
            int j  = idx >> 4;
            int d4 = idx & 15;
            ((float4*)Ks[j])[d4] = *(const float4*)(Kg + base + (size_t)j * En + d4 * 4);
            ((float4*)Vs[j])[d4] = *(const float4*)(Vg + base + (size_t)j * En + d4 * 4);
        }
        __syncthreads();

        float s[KT];                         // local-mem OK (L1-resident)
        float tmax = -1e30f;
        const int kbase = kt * KT;
#pragma unroll 4
        for (int j = 0; j < KT; ++j) {
            const float4* kr = (const float4*)Ks[j];
            float sj = 0.f;
#pragma unroll
            for (int d = 0; d < 16; ++d) {
                float4 k4 = kr[d];
                sj = fmaf(q4[d].x, k4.x, sj);
                sj = fmaf(q4[d].y, k4.y, sj);
                sj = fmaf(q4[d].z, k4.z, sj);
                sj = fmaf(q4[d].w, k4.w, sj);
            }
            sj *= 0.125f;                              // 1/sqrt(64)
            sj = (kbase + j <= qg) ? sj : -1e30f;      // causal mask
            s[j] = sj;
            tmax = fmaxf(tmax, sj);
        }

        float mnew = fmaxf(mi, tmax);
        float corr = __expf(mi - mnew);
        l *= corr;
#pragma unroll
        for (int d = 0; d < 16; ++d) {
            o4[d].x *= corr; o4[d].y *= corr; o4[d].z *= corr; o4[d].w *= corr;
        }
#pragma unroll 4
        for (int j = 0; j < KT; ++j) {
            float p = __expf(s[j] - mnew);
            l += p;
            const float4* vr = (const float4*)Vs[j];
#pragma unroll
            for (int d = 0; d < 16; ++d) {
                float4 v4 = vr[d];
                o4[d].x = fmaf(p, v4.x, o4[d].x);
                o4[d].y = fmaf(p, v4.y, o4[d].y);
                o4[d].z = fmaf(p, v4.z, o4[d].z);
                o4[d].w = fmaf(p, v4.w, o4[d].w);
            }
        }
        mi = mnew;
        __syncthreads();
    }

    float inv = 1.f / l;
    float4* op = (float4*)(Og + ((size_t)(b * Sn + qg)) * En + h * Dn);
#pragma unroll
    for (int i = 0; i < 16; ++i) {
        float4 v = o4[i];
        v.x *= inv; v.y *= inv; v.z *= inv; v.w *= inv;
        op[i] = v;
    }
}

// ---------------------------------------------------------------------------
// Final head: out[m] = X[m,:] . W_out[:,0] + b_out   (warp per row)
// ---------------------------------------------------------------------------
__global__ void head_kernel(const float* __restrict__ X,
                            const float* __restrict__ Wout,
                            const float* __restrict__ bout,
                            float* __restrict__ out) {
    int gw = (blockIdx.x * blockDim.x + threadIdx.x) >> 5;
    int lane = threadIdx.x & 31;
    if (gw >= Mn) return;
    const float4* xr = (const float4*)(X + (size_t)gw * En);
    const float4* w4 = (const float4*)Wout;
    float acc = 0.f;
#pragma unroll
    for (int i = 0; i < 4; ++i) {
        float4 xv = xr[lane + i * 32];
        float4 wv = w4[lane + i * 32];
        acc += xv.x * wv.x + xv.y * wv.y + xv.z * wv.z + xv.w * wv.w;
    }
#pragma unroll
    for (int o = 16; o > 0; o >>= 1)
        acc += __shfl_xor_sync(0xffffffffu, acc, o);
    if (lane == 0) out[gw] = acc + bout[0];
}

// ---------------------------------------------------------------------------
// Launch
// ---------------------------------------------------------------------------
extern "C" void kernel_launch(void* const* d_in, const int* in_sizes, int n_in,
                              void* d_out, int out_size) {
    const int*   tok   = (const int*)d_in[0];
    const float* table = (const float*)d_in[1];
    const float* Wq    = (const float*)d_in[2];
    const float* bq    = (const float*)d_in[3];
    const float* Wk    = (const float*)d_in[4];
    const float* bk    = (const float*)d_in[5];
    const float* Wv    = (const float*)d_in[6];
    const float* bv    = (const float*)d_in[7];
    const float* Wo    = (const float*)d_in[8];
    const float* bo    = (const float*)d_in[9];
    const float* Wout  = (const float*)d_in[10];
    const float* bout  = (const float*)d_in[11];
    float* out = (float*)d_out;

    void* base = nullptr;
    cudaGetSymbolAddress(&base, g_buf);   // not a stream op: capture-safe
    float* X  = (float*)base;
    float* Qb = X + ME;
    float* Kb = X + 2 * ME;
    float* Vb = X + 3 * ME;
    float* Ab = X + 4 * ME;
    float* PE = X + 5 * ME;

    pe_kernel<<<(Sn * En + 255) / 256, 256>>>(PE);
    embed_kernel<<<(Mn * (En / 4) + 255) / 256, 256>>>(tok, table, PE, X);

    dim3 gg(En / 128, Mn / 128);   // (4, 256)
    dim3 ag(Sn / 128, Hn, Bn);     // (8, 8, 32)
    for (int l = 0; l < Ln; ++l) {
        const float* wq = Wq + (size_t)l * En * En; const float* bql = bq + l * En;
        const float* wk = Wk + (size_t)l * En * En; const float* bkl = bk + l * En;
        const float* wv = Wv + (size_t)l * En * En; const float* bvl = bv + l * En;
        const float* wo = Wo + (size_t)l * En * En; const float* bol = bo + l * En;
        gemm512<false><<<gg, 256>>>(X,  wq, bql, nullptr, Qb);
        gemm512<false><<<gg, 256>>>(X,  wk, bkl, nullptr, Kb);
        gemm512<false><<<gg, 256>>>(X,  wv, bvl, nullptr, Vb);
        attn_kernel<<<ag, 128>>>(Qb, Kb, Vb, Ab);
        gemm512<true><<<gg, 256>>>(Ab, wo, bol, X, X);   // X = X + relu(attn@Wo+bo)
    }
    head_kernel<<<(Mn * 32 + 255) / 256, 256>>>(X, Wout, bout, out);
}